// round 1
// baseline (speedup 1.0000x reference)
#include <cuda_runtime.h>

#define DD 128
#define MAXN 100000
#define NBLK_E 1184
#define TPB_E 256
#define WPB 8
#define BN_EPS 1e-5f

// ---------------- device scratch (no allocation allowed) ----------------
__device__ float g_u[MAXN * DD];                 // x @ W1[:, :128].T   (51.2 MB)
__device__ float g_v[MAXN * DD];                 // x @ W1[:, 128:].T   (51.2 MB)
__device__ float g_part[NBLK_E * 256];           // per-block [sum(128) | sumsq(128)]
__device__ float g_a[DD];                        // BN scale
__device__ float g_c[DD];                        // BN shift
__device__ int   g_idx64;                        // edge_index dtype flag

// ---------------- dtype detect: int64 edge_index has zero high words ----
__global__ void detect_idx_kernel(const int* __restrict__ ei) {
    int z = 0;
#pragma unroll
    for (int i = 0; i < 16; i++) z |= ei[2 * i + 1];   // high dwords if int64
    g_idx64 = (z == 0) ? 1 : 0;
}

// ---------------- node GEMM: u,v = x @ [W1a|W1b].T ----------------------
// Block = 64 nodes x 256 output features. Thread: 8 nodes x 8 features.
// smem: W1 k-tile transposed [32][260] + x tile transposed [32][68]. 41.98 KB.
__global__ __launch_bounds__(256) void node_gemm_kernel(
    const float* __restrict__ x, const float* __restrict__ W1, int N) {
    __shared__ float w1s[32 * 260];
    __shared__ float xs[32 * 68];

    const int tid = threadIdx.x;
    const int base = blockIdx.x * 64;
    const int fg = tid & 31;       // feature group: feats fg*8 .. fg*8+7 (of 256)
    const int ng = tid >> 5;       // node group:    nodes ng*8 .. ng*8+7 (of 64)
    const int f0 = fg * 8, n0 = ng * 8;

    float acc[8][8];
#pragma unroll
    for (int n = 0; n < 8; n++)
#pragma unroll
        for (int f = 0; f < 8; f++) acc[n][f] = 0.f;

    for (int kb = 0; kb < 128; kb += 32) {
        __syncthreads();
        // W1 tile: read coalesced row-major, write transposed [k][f]
#pragma unroll
        for (int it = 0; it < 32; it++) {
            int idx = it * 256 + tid;
            int j = idx >> 6;            // 0..127 (W1 row)
            int cc = idx & 63;
            int kl = cc & 31;
            int half = cc >> 5;          // 0: u-half, 1: v-half
            float val = W1[j * 256 + kb + kl + (half << 7)];
            w1s[kl * 260 + j + (half << 7)] = val;
        }
        // x tile transposed [k][n]
#pragma unroll
        for (int it = 0; it < 8; it++) {
            int idx = it * 256 + tid;
            int n = idx >> 5;
            int kl = idx & 31;
            int node = base + n;
            xs[kl * 68 + n] = (node < N) ? x[node * 128 + kb + kl] : 0.f;
        }
        __syncthreads();
#pragma unroll
        for (int k = 0; k < 32; k++) {
            float4 wa = *(const float4*)&w1s[k * 260 + f0];
            float4 wb = *(const float4*)&w1s[k * 260 + f0 + 4];
            float4 xa = *(const float4*)&xs[k * 68 + n0];
            float4 xb = *(const float4*)&xs[k * 68 + n0 + 4];
            float wv[8] = {wa.x, wa.y, wa.z, wa.w, wb.x, wb.y, wb.z, wb.w};
            float xv[8] = {xa.x, xa.y, xa.z, xa.w, xb.x, xb.y, xb.z, xb.w};
#pragma unroll
            for (int n = 0; n < 8; n++)
#pragma unroll
                for (int f = 0; f < 8; f++)
                    acc[n][f] = fmaf(xv[n], wv[f], acc[n][f]);
        }
    }

    float* dstbase = (fg < 16) ? g_u : g_v;
    const int fo = (fg < 16) ? f0 : (f0 - 128);
#pragma unroll
    for (int n = 0; n < 8; n++) {
        int node = base + n0 + n;
        if (node < N) {
            float4 o1 = make_float4(acc[n][0], acc[n][1], acc[n][2], acc[n][3]);
            float4 o2 = make_float4(acc[n][4], acc[n][5], acc[n][6], acc[n][7]);
            *(float4*)&dstbase[node * 128 + fo] = o1;
            *(float4*)&dstbase[node * 128 + fo + 4] = o2;
        }
    }
}

// ---------------- edge pass 1: per-feature sum / sumsq of w=u[s]+v[d] ---
__global__ __launch_bounds__(TPB_E) void edge_stats_kernel(
    const long long* __restrict__ ei, int E, int totalWarps) {
    const int lane = threadIdx.x & 31;
    const int wid = threadIdx.x >> 5;
    const int gw = blockIdx.x * WPB + wid;
    const int is64 = g_idx64;

    float4 s = make_float4(0, 0, 0, 0);
    float4 q = make_float4(0, 0, 0, 0);

    for (int e = gw; e < E; e += totalWarps) {
        int src, dst;
        if (is64) {
            longlong2 p = ((const longlong2*)ei)[e];
            src = (int)p.x; dst = (int)p.y;
        } else {
            int2 p = ((const int2*)ei)[e];
            src = p.x; dst = p.y;
        }
        float4 uu = *(const float4*)&g_u[src * 128 + lane * 4];
        float4 vv = *(const float4*)&g_v[dst * 128 + lane * 4];
        float w0 = uu.x + vv.x, w1 = uu.y + vv.y, w2 = uu.z + vv.z, w3 = uu.w + vv.w;
        s.x += w0; s.y += w1; s.z += w2; s.w += w3;
        q.x = fmaf(w0, w0, q.x); q.y = fmaf(w1, w1, q.y);
        q.z = fmaf(w2, w2, q.z); q.w = fmaf(w3, w3, q.w);
    }

    __shared__ float red[WPB * 256];
    float* r = red + wid * 256 + lane * 4;
    r[0] = s.x; r[1] = s.y; r[2] = s.z; r[3] = s.w;
    r[128] = q.x; r[129] = q.y; r[130] = q.z; r[131] = q.w;
    __syncthreads();
    int j = threadIdx.x;  // 0..255
    float t = 0.f;
#pragma unroll
    for (int w = 0; w < WPB; w++) t += red[w * 256 + j];
    g_part[blockIdx.x * 256 + j] = t;
}

// ---------------- finalize BN affine: a,c (b1 cancels out) --------------
__global__ void finalize_stats_kernel(const float* __restrict__ gamma,
                                      const float* __restrict__ beta,
                                      float invE) {
    int j = threadIdx.x;  // 128 threads
    float s = 0.f, q = 0.f;
    for (int b = 0; b < NBLK_E; b++) {
        s += g_part[b * 256 + j];
        q += g_part[b * 256 + 128 + j];
    }
    float mean = s * invE;
    float var = fmaf(-mean, mean, q * invE);
    float a = gamma[j] * rsqrtf(var + BN_EPS);
    g_a[j] = a;
    g_c[j] = fmaf(-a, mean, beta[j]);
}

// ---------------- edge pass 2: out = relu(a*(u+v)+c) @ W2.T + b2 --------
__global__ __launch_bounds__(TPB_E) void edge_out_kernel(
    const long long* __restrict__ ei, const float* __restrict__ W2,
    const float* __restrict__ b2, float* __restrict__ out,
    int E, int totalWarps) {
    const int lane = threadIdx.x & 31;
    const int gw = blockIdx.x * WPB + (threadIdx.x >> 5);
    const int is64 = g_idx64;

    float4 a4 = *(const float4*)&g_a[lane * 4];
    float4 c4 = *(const float4*)&g_c[lane * 4];
    float4 wA = *(const float4*)&W2[lane * 4];
    float4 wB = *(const float4*)&W2[128 + lane * 4];
    float bz0 = b2[0], bz1 = b2[1];

    for (int e = gw; e < E; e += totalWarps) {
        int src, dst;
        if (is64) {
            longlong2 p = ((const longlong2*)ei)[e];
            src = (int)p.x; dst = (int)p.y;
        } else {
            int2 p = ((const int2*)ei)[e];
            src = p.x; dst = p.y;
        }
        float4 uu = *(const float4*)&g_u[src * 128 + lane * 4];
        float4 vv = *(const float4*)&g_v[dst * 128 + lane * 4];
        float r0 = fmaxf(fmaf(a4.x, uu.x + vv.x, c4.x), 0.f);
        float r1 = fmaxf(fmaf(a4.y, uu.y + vv.y, c4.y), 0.f);
        float r2 = fmaxf(fmaf(a4.z, uu.z + vv.z, c4.z), 0.f);
        float r3 = fmaxf(fmaf(a4.w, uu.w + vv.w, c4.w), 0.f);
        float p0 = r0 * wA.x + r1 * wA.y + r2 * wA.z + r3 * wA.w;
        float p1 = r0 * wB.x + r1 * wB.y + r2 * wB.z + r3 * wB.w;
#pragma unroll
        for (int o = 16; o > 0; o >>= 1) {
            p0 += __shfl_xor_sync(0xFFFFFFFFu, p0, o);
            p1 += __shfl_xor_sync(0xFFFFFFFFu, p1, o);
        }
        if (lane == 0)
            ((float2*)out)[e] = make_float2(p0 + bz0, p1 + bz1);
    }
}

// ---------------- launch ------------------------------------------------
extern "C" void kernel_launch(void* const* d_in, const int* in_sizes, int n_in,
                              void* d_out, int out_size) {
    const float* x = (const float*)d_in[0];
    const long long* ei = (const long long*)d_in[1];
    const float* W1 = (const float*)d_in[2];
    // d_in[3] = b1 : cancels inside BatchNorm, unused
    const float* gamma = (const float*)d_in[4];
    const float* beta = (const float*)d_in[5];
    const float* W2 = (const float*)d_in[6];
    const float* b2 = (const float*)d_in[7];

    const int N = in_sizes[0] / DD;
    const int E = in_sizes[1] / 2;
    const int totalWarps = NBLK_E * WPB;

    detect_idx_kernel<<<1, 1>>>((const int*)ei);
    node_gemm_kernel<<<(N + 63) / 64, 256>>>(x, W1, N);
    edge_stats_kernel<<<NBLK_E, TPB_E>>>(ei, E, totalWarps);
    finalize_stats_kernel<<<1, 128>>>(gamma, beta, 1.0f / (float)E);
    edge_out_kernel<<<NBLK_E, TPB_E>>>(ei, W2, b2, (float*)d_out, E, totalWarps);
}